// round 7
// baseline (speedup 1.0000x reference)
#include <cuda_runtime.h>
#include <cuda_bf16.h>
#include <cstdint>

// QuantumConvLayer: out[b, 2j]   = cos(q[2j]) * cos(pi * x[b, 2j])
//                   out[b, 2j+1] = out[b, 2j] * cos(q[2j+1] + pi * x[b, 2j+1])
// B = 4194304, N_QUBITS = 16. Streaming HBM-bound elementwise map.
//
// Round 6: persistent grid-stride kernel with software-prefetch double
// buffering. Each resident warp keeps loads for the NEXT tile in flight while
// computing/storing the current tile -> sustained (not bursty) MLP, higher
// steady-state DRAM occupancy. Tile = 512 float4 (256 threads x 2); q index
// is tid&3 invariant across the whole loop.

#define QCONV_THREADS 256
#define QCONV_VEC     2                               // float4 per thread per tile
#define QCONV_TILE    (QCONV_THREADS * QCONV_VEC)     // 512 float4 per tile

__device__ __forceinline__ float4 qconv_compute(
    const float4 xv, float ce0, float ce1, float qo0, float qo1)
{
    const float PI = 3.14159265358979323846f;
    float z0 = ce0 * __cosf(PI * xv.x);
    float o0 = z0 * __cosf(qo0 + PI * xv.y);
    float z1 = ce1 * __cosf(PI * xv.z);
    float o1 = z1 * __cosf(qo1 + PI * xv.w);
    return make_float4(z0, o0, z1, o1);
}

__global__ __launch_bounds__(QCONV_THREADS) void qconv_persistent(
    const float4* __restrict__ x4,
    const float4* __restrict__ q4,
    float4* __restrict__ out4,
    int n_tiles)                      // n4 / QCONV_TILE (n4 % QCONV_TILE == 0)
{
    const int tid = threadIdx.x;
    const int gstride = gridDim.x;

    // tile*512 + k*256 + tid  ->  & 3 == tid & 3 always
    float4 qv = q4[tid & 3];
    float ce0 = __cosf(qv.x);
    float ce1 = __cosf(qv.z);

    int t = blockIdx.x;
    if (t >= n_tiles) return;

    // Prime the pipeline: loads for the first tile
    const float4* p = x4 + t * QCONV_TILE + tid;
    float4 a0 = __ldcs(p);
    float4 a1 = __ldcs(p + QCONV_THREADS);

    while (true) {
        int tn = t + gstride;
        float4 b0, b1;
        bool more = (tn < n_tiles);
        if (more) {
            // Prefetch next tile BEFORE consuming current one
            const float4* pn = x4 + tn * QCONV_TILE + tid;
            b0 = __ldcs(pn);
            b1 = __ldcs(pn + QCONV_THREADS);
        }

        // Compute + store current tile (loads for next tile already in flight)
        float4 r0 = qconv_compute(a0, ce0, ce1, qv.y, qv.w);
        float4 r1 = qconv_compute(a1, ce0, ce1, qv.y, qv.w);
        float4* po = out4 + t * QCONV_TILE + tid;
        __stcs(po, r0);
        __stcs(po + QCONV_THREADS, r1);

        if (!more) break;
        a0 = b0; a1 = b1; t = tn;
    }
}

// Fallback for sizes not divisible by the tile (simple guarded map).
__global__ __launch_bounds__(QCONV_THREADS) void qconv_guarded(
    const float4* __restrict__ x4,
    const float4* __restrict__ q4,
    float4* __restrict__ out4,
    int n4)
{
    int i = blockIdx.x * blockDim.x + threadIdx.x;
    if (i >= n4) return;
    float4 qv = q4[i & 3];
    float4 r = qconv_compute(__ldcs(x4 + i), __cosf(qv.x), __cosf(qv.z), qv.y, qv.w);
    __stcs(out4 + i, r);
}

extern "C" void kernel_launch(void* const* d_in, const int* in_sizes, int n_in,
                              void* d_out, int out_size)
{
    const float4* x4 = (const float4*)d_in[0];      // x: [B, 16] float32
    const float4* q4 = (const float4*)d_in[1];      // q_params: [16] float32
    float4* out4 = (float4*)d_out;

    int n4 = out_size / 4;                           // 16,777,216

    if (n4 % QCONV_TILE == 0) {
        int n_tiles = n4 / QCONV_TILE;               // 32,768
        int blocks = 148 * 8;                        // persistent: 8 CTAs/SM
        if (blocks > n_tiles) blocks = n_tiles;
        qconv_persistent<<<blocks, QCONV_THREADS>>>(x4, q4, out4, n_tiles);
    } else {
        int blocks = (n4 + QCONV_THREADS - 1) / QCONV_THREADS;
        qconv_guarded<<<blocks, QCONV_THREADS>>>(x4, q4, out4, n4);
    }
}

// round 9
// speedup vs baseline: 1.1089x; 1.1089x over previous
#include <cuda_runtime.h>
#include <cuda_bf16.h>
#include <cstdint>

// QuantumConvLayer: out[b, 2j]   = cos(q[2j]) * cos(pi * x[b, 2j])
//                   out[b, 2j+1] = out[b, 2j] * cos(q[2j+1] + pi * x[b, 2j+1])
// B = 4194304, N_QUBITS = 16. Streaming HBM-bound elementwise map.
//
// Round 8: back to the proven R2 burst structure (front-batched LDG.128,
// block-tiled, streaming hints), with load depth doubled: UNROLL=8.
// All 8 independent 16B loads issue up front (MLP_p1=8/thread); each result
// is computed and stored immediately to keep live registers ~40 so occupancy
// stays at ~6 CTAs/SM.

#define QCONV_THREADS 256
#define QCONV_UNROLL  8
#define QCONV_TILE    (QCONV_THREADS * QCONV_UNROLL)   // 2048 float4 per block

__global__ __launch_bounds__(QCONV_THREADS) void qconv_kernel(
    const float4* __restrict__ x4,
    const float4* __restrict__ q4,   // q_params viewed as 4x float4
    float4* __restrict__ out4,
    int n4)
{
    const float PI = 3.14159265358979323846f;
    int base = blockIdx.x * QCONV_TILE + threadIdx.x;

    // (base + k*256) & 3 == base & 3 for all k (256 % 4 == 0)
    float4 qv = q4[base & 3];
    float ce0 = __cosf(qv.x);   // invariant across unroll
    float ce1 = __cosf(qv.z);

    // Front-batch all 8 independent 16B loads (MLP_p1 = 8 per thread)
    float4 xv[QCONV_UNROLL];
#pragma unroll
    for (int k = 0; k < QCONV_UNROLL; k++) {
        int idx = base + k * QCONV_THREADS;
        xv[k] = (idx < n4) ? __ldcs(x4 + idx) : make_float4(0.f, 0.f, 0.f, 0.f);
    }

    // Compute + store each result immediately (short result live-range)
#pragma unroll
    for (int k = 0; k < QCONV_UNROLL; k++) {
        float z0 = ce0 * __cosf(PI * xv[k].x);
        float o0 = z0 * __cosf(qv.y + PI * xv[k].y);
        float z1 = ce1 * __cosf(PI * xv[k].z);
        float o1 = z1 * __cosf(qv.w + PI * xv[k].w);
        int idx = base + k * QCONV_THREADS;
        if (idx < n4) __stcs(out4 + idx, make_float4(z0, o0, z1, o1));
    }
}

extern "C" void kernel_launch(void* const* d_in, const int* in_sizes, int n_in,
                              void* d_out, int out_size)
{
    const float4* x4 = (const float4*)d_in[0];      // x: [B, 16] float32
    const float4* q4 = (const float4*)d_in[1];      // q_params: [16] float32
    float4* out4 = (float4*)d_out;

    int n4 = out_size / 4;                           // 16,777,216
    int blocks = (n4 + QCONV_TILE - 1) / QCONV_TILE; // 8,192

    qconv_kernel<<<blocks, QCONV_THREADS>>>(x4, q4, out4, n4);
}